// round 14
// baseline (speedup 1.0000x reference)
#include <cuda_runtime.h>
#include <cstdint>

#define NIMG   8
#define NANCH  25200
#define NCH    85
#define NC     80
#define MAXC   2048
#define CAPK   4096
#define BCAP   64
#define DET    300
#define CONF   0.96f
#define IOUT   0.45f
#define FULLM  0xffffffffu

#define CF_GRID 148   // padded to a full wave

// ---------------- device scratch (no allocations allowed) ----------------
__device__ int g_count[NIMG];
__device__ int g_bcnt[NIMG * NC];
__device__ int g_kcnt[NIMG];
__device__ int g_slow[NIMG];
__device__ unsigned long long g_keys[NIMG][CAPK];
__device__ unsigned long long g_bucket[NIMG * NC][BCAP];
__device__ unsigned long long g_kept[NIMG][MAXC];

// ---------------- K1: candidate extraction (proven, unchanged) ----------------
__global__ void __launch_bounds__(256) k_extract(const float* __restrict__ pred) {
    const int img  = blockIdx.y;
    const int warp = threadIdx.x >> 5;
    const int lane = threadIdx.x & 31;
    const int abase = blockIdx.x * 256 + warp * 32;

    __shared__ unsigned long long sbuf[1024];
    __shared__ int sn, sbase;
    if (threadIdx.x == 0) sn = 0;
    __syncthreads();

    int a = abase + lane;
    float obj = 0.0f;
    if (a < NANCH) obj = pred[((size_t)img * NANCH + a) * NCH + 4];

    unsigned mask = __ballot_sync(FULLM, obj > CONF);
    while (mask) {
        bool  val[4]; int aa[4]; float oo[4];
        #pragma unroll
        for (int u = 0; u < 4; u++) {
            val[u] = (mask != 0);
            int i = 0;
            if (mask) { i = __ffs(mask) - 1; mask &= mask - 1; }
            aa[u] = abase + i;
            oo[u] = __shfl_sync(FULLM, obj, i);
        }
        float v0[4], v1[4], v2[4];
        #pragma unroll
        for (int u = 0; u < 4; u++) {
            const float* row = pred + ((size_t)img * NANCH + aa[u]) * NCH;
            v0[u] = val[u] ? row[5  + lane] : 0.0f;
            v1[u] = val[u] ? row[37 + lane] : 0.0f;
            v2[u] = (val[u] && lane < 16) ? row[69 + lane] : 0.0f;
        }
        #pragma unroll
        for (int u = 0; u < 4; u++) {
            if (!val[u]) continue;                      // warp-uniform
            #pragma unroll
            for (int cc = 0; cc < 3; cc++) {
                int c = lane + cc * 32;
                float v = (cc == 0) ? v0[u] : (cc == 1) ? v1[u] : v2[u];
                if (c < NC) {
                    float s = __fmul_rn(v, oo[u]);      // matches XLA rn mul
                    if (s > CONF) {
                        unsigned long long key =
                            ((unsigned long long)__float_as_uint(s) << 32) |
                            (unsigned long long)(0xFFFFFFFFu - (unsigned)(aa[u] * NC + c));
                        int bi = img * NC + c;
                        int bp = atomicAdd(&g_bcnt[bi], 1);
                        if (bp < BCAP) g_bucket[bi][bp] = key;
                        int lp = atomicAdd(&sn, 1);
                        if (lp < 1024) sbuf[lp] = key;
                        else {
                            int gp = atomicAdd(&g_count[img], 1);
                            if (gp < CAPK) g_keys[img][gp] = key;
                        }
                    }
                }
            }
        }
    }
    __syncthreads();
    int n = min(sn, 1024);
    if (threadIdx.x == 0) sbase = atomicAdd(&g_count[img], n);
    __syncthreads();
    for (int i = threadIdx.x; i < n; i += 256) {
        int gp = sbase + i;
        if (gp < CAPK) g_keys[img][gp] = sbuf[i];
    }
}

// ---------------- exact IoU matching the reference fp32 sequence ----------------
__device__ __forceinline__ bool iou_gt(const float4 A, const float areaA, const float4 B) {
    float ltx = fmaxf(A.x, B.x), lty = fmaxf(A.y, B.y);
    float rbx = fminf(A.z, B.z), rby = fminf(A.w, B.w);
    float wx = fmaxf(__fsub_rn(rbx, ltx), 0.0f);
    float wy = fmaxf(__fsub_rn(rby, lty), 0.0f);
    float inter = __fmul_rn(wx, wy);
    float areaB = __fmul_rn(__fsub_rn(B.z, B.x), __fsub_rn(B.w, B.y));
    float denom = __fadd_rn(__fsub_rn(__fadd_rn(areaA, areaB), inter), 1e-9f);
    return __fdiv_rn(inter, denom) > IOUT;
}

__device__ __forceinline__ unsigned long long cmpswap64(unsigned long long v, int j,
                                                        bool desc, int idx) {
    unsigned long long x = __shfl_xor_sync(FULLM, v, j);
    bool lower = (idx & j) == 0;
    bool takeMax = (lower == desc);
    return takeMax ? (v > x ? v : x) : (v < x ? v : x);
}

__device__ __forceinline__ void decode_off(const float* __restrict__ pred, int img,
                                           unsigned long long key, float4* ob, float* ar) {
    unsigned flat = 0xFFFFFFFFu - (unsigned)key;
    int anchor = (int)(flat / NC);
    int l = (int)flat - anchor * NC;
    const float* row = pred + ((size_t)img * NANCH + anchor) * NCH;
    float cx = row[0], cy = row[1], w = row[2], h = row[3];
    float hw = __fmul_rn(0.5f, w), hh = __fmul_rn(0.5f, h);
    float off = __fmul_rn((float)l, 4.0f);
    ob->x = __fadd_rn(__fsub_rn(cx, hw), off);
    ob->y = __fadd_rn(__fsub_rn(cy, hh), off);
    ob->z = __fadd_rn(__fadd_rn(cx, hw), off);
    ob->w = __fadd_rn(__fadd_rn(cy, hh), off);
    *ar = __fmul_rn(__fsub_rn(ob->z, ob->x), __fsub_rn(ob->w, ob->y));
}

// warp-level register NMS for one (img,class)
__device__ void class_nms(const float* __restrict__ pred, int img, int c, int lane) {
    const int bi = img * NC + c;
    const int kk = g_bcnt[bi];
    if (kk > BCAP) { if (lane == 0) g_slow[img] = 1; return; }
    if (kk == 0) return;

    if (kk <= 32) {
        unsigned long long v0 = (lane < kk) ? g_bucket[bi][lane] : 0ULL;
        #pragma unroll
        for (int k = 2; k <= 32; k <<= 1)
            #pragma unroll
            for (int j = k >> 1; j > 0; j >>= 1)
                v0 = cmpswap64(v0, j, (lane & k) == 0, lane);

        float4 ob0 = make_float4(0.f,0.f,0.f,0.f);
        float ar0 = 0.f;
        if (lane < kk) decode_off(pred, img, v0, &ob0, &ar0);

        unsigned m0 = 0u;
        for (int t = 1; t < kk; t++) {
            float4 B;
            B.x = __shfl_sync(FULLM, ob0.x, t); B.y = __shfl_sync(FULLM, ob0.y, t);
            B.z = __shfl_sync(FULLM, ob0.z, t); B.w = __shfl_sync(FULLM, ob0.w, t);
            if (lane < t && iou_gt(ob0, ar0, B)) m0 |= 1u << t;
        }
        unsigned alive = (kk >= 32) ? 0xFFFFFFFFu : ((1u << kk) - 1u);
        for (int t = 0; t < kk; t++) {
            unsigned mt = __shfl_sync(FULLM, m0, t);
            if ((alive >> t) & 1u) alive &= ~mt;
        }
        bool k0 = (lane < kk) && ((alive >> lane) & 1u);
        unsigned b0 = __ballot_sync(FULLM, k0);
        int tot = __popc(b0);
        int base = 0;
        if (lane == 0 && tot) base = atomicAdd(&g_kcnt[img], tot);
        base = __shfl_sync(FULLM, base, 0);
        if (k0) {
            int p = base + __popc(b0 & ((1u << lane) - 1u));
            if (p < MAXC) g_kept[img][p] = v0;
        }
        return;
    }

    // ---------- 64-wide path (rare) ----------
    unsigned long long v0 = (lane      < kk) ? g_bucket[bi][lane]      : 0ULL;
    unsigned long long v1 = (lane + 32 < kk) ? g_bucket[bi][lane + 32] : 0ULL;
    #pragma unroll
    for (int k = 2; k <= 64; k <<= 1) {
        #pragma unroll
        for (int j = k >> 1; j > 0; j >>= 1) {
            if (j >= 32) {
                unsigned long long a = v0 > v1 ? v0 : v1;
                unsigned long long b = v0 > v1 ? v1 : v0;
                v0 = a; v1 = b;
            } else {
                v0 = cmpswap64(v0, j, ((lane       & k) == 0), lane);
                v1 = cmpswap64(v1, j, (((lane + 32) & k) == 0), lane);
            }
        }
    }
    float4 ob0 = make_float4(0.f,0.f,0.f,0.f), ob1 = ob0;
    float ar0 = 0.f, ar1 = 0.f;
    if (lane      < kk) decode_off(pred, img, v0, &ob0, &ar0);
    if (lane + 32 < kk) decode_off(pred, img, v1, &ob1, &ar1);
    unsigned long long m0 = 0ULL, m1 = 0ULL;
    for (int t = 0; t < kk; t++) {
        int sl = t & 31;
        float4 B;
        if (t >= 32) {
            B.x = __shfl_sync(FULLM, ob1.x, sl); B.y = __shfl_sync(FULLM, ob1.y, sl);
            B.z = __shfl_sync(FULLM, ob1.z, sl); B.w = __shfl_sync(FULLM, ob1.w, sl);
        } else {
            B.x = __shfl_sync(FULLM, ob0.x, sl); B.y = __shfl_sync(FULLM, ob0.y, sl);
            B.z = __shfl_sync(FULLM, ob0.z, sl); B.w = __shfl_sync(FULLM, ob0.w, sl);
        }
        if (lane < t && lane < kk && iou_gt(ob0, ar0, B)) m0 |= 1ULL << t;
        if (lane + 32 < t && iou_gt(ob1, ar1, B))         m1 |= 1ULL << t;
    }
    unsigned long long alive = (kk >= 64) ? ~0ULL : ((1ULL << kk) - 1ULL);
    for (int t = 0; t < kk; t++) {
        unsigned long long mt = __shfl_sync(FULLM, (t >= 32) ? m1 : m0, t & 31);
        if ((alive >> t) & 1ULL) alive &= ~mt;
    }
    bool k0 = (lane      < kk) && ((alive >> lane) & 1ULL);
    bool k1 = (lane + 32 < kk) && ((alive >> (lane + 32)) & 1ULL);
    unsigned b0 = __ballot_sync(FULLM, k0);
    unsigned b1 = __ballot_sync(FULLM, k1);
    int tot = __popc(b0) + __popc(b1);
    int base = 0;
    if (lane == 0 && tot) base = atomicAdd(&g_kcnt[img], tot);
    base = __shfl_sync(FULLM, base, 0);
    unsigned lt = (1u << lane) - 1u;
    if (k0) { int p = base + __popc(b0 & lt);              if (p < MAXC) g_kept[img][p] = v0; }
    if (k1) { int p = base + __popc(b0) + __popc(b1 & lt); if (p < MAXC) g_kept[img][p] = v1; }
}

// ---------------- block bitonic (descending, smem) ----------------
__device__ __forceinline__ void bitonic_desc(unsigned long long* a, int n, int tid, int nthreads) {
    for (int k = 2; k <= n; k <<= 1) {
        for (int j = k >> 1; j > 0; j >>= 1) {
            __syncthreads();
            for (int i = tid; i < n; i += nthreads) {
                int p = i ^ j;
                if (p > i) {
                    bool up = (i & k) == 0;
                    unsigned long long x = a[i], y = a[p];
                    bool sw = up ? (x < y) : (x > y);
                    if (sw) { a[i] = y; a[p] = x; }
                }
            }
        }
    }
    __syncthreads();
}

// ---------------- smem layout (sized for the slow path) ----------------
#define OFF_KEYS   0        // u64[4096]
#define OFF_RAWB   32768    // float4[2048]
#define OFF_OFFB   65536    // float4[2048]
#define OFF_LAB    98304    // u8[2048]
#define OFF_KEEP   100352   // u8[2048]
#define OFF_CLIST  102400   // u16[2048]
#define OFF_CNT    106496   // int[80]
#define OFF_START  106816   // int[80]
#define OFF_CNT2   107136   // int[80]
#define OFF_MISC   107456   // int[16]
#define SMEM_TOTAL 107520

// ---------------- K2: fused per-image class-NMS + final sort + emit ----------
__global__ void __launch_bounds__(1024, 1) k_cf(const float* __restrict__ pred,
                                                float* __restrict__ out) {
    const int img = blockIdx.x;
    if (img >= NIMG) return;                 // padding blocks: exit immediately

    extern __shared__ unsigned char smem[];
    unsigned long long* keys = (unsigned long long*)(smem + OFF_KEYS);

    const int tid  = threadIdx.x;
    const int warp = tid >> 5;
    const int lane = tid & 31;
    const int count = g_count[img];

    // ---- phase C: warp-per-class register NMS (3 indep chains per warp) ----
    if (count <= MAXC) {
        for (int c = warp; c < NC; c += 32)
            class_nms(pred, img, c, lane);
    }
    __syncthreads();   // block-wide fence: g_kept/g_kcnt/g_slow visible

    // ---- phase F: final sort + emit ----
    const bool slow = (count > MAXC) || (g_slow[img] != 0);
    const int n = min(g_kcnt[img], MAXC);

    if (!slow && n <= 1024) {
        // fast path: hybrid register/smem bitonic over 1024 (g_kept hits L1)
        unsigned long long v = (tid < n) ? g_kept[img][tid] : 0ULL;
        unsigned long long* b0 = keys;
        unsigned long long* b1 = keys + 1024;
        int pp = 0;
        #pragma unroll
        for (int k = 2; k <= 1024; k <<= 1) {
            int j = k >> 1;
            for (; j >= 32; j >>= 1) {
                unsigned long long* buf = pp ? b1 : b0; pp ^= 1;
                buf[tid] = v;
                __syncthreads();
                unsigned long long x = buf[tid ^ j];
                bool lower = (tid & j) == 0;
                bool desc  = (tid & k) == 0;
                bool takeMax = (lower == desc);
                v = takeMax ? (v > x ? v : x) : (v < x ? v : x);
            }
            for (; j > 0; j >>= 1)
                v = cmpswap64(v, j, (tid & k) == 0, tid);
        }
        if (tid < DET) {
            float o0=0.f,o1=0.f,o2=0.f,o3=0.f,o4=0.f,o5=0.f;
            if (v != 0ULL) {
                unsigned flat = 0xFFFFFFFFu - (unsigned)v;
                int anchor = (int)(flat / NC);
                int l = (int)flat - anchor * NC;
                const float* row = pred + ((size_t)img * NANCH + anchor) * NCH;
                float cx = row[0], cy = row[1], w = row[2], h = row[3];
                float hw = __fmul_rn(0.5f, w), hh = __fmul_rn(0.5f, h);
                o0 = __fsub_rn(cx, hw); o1 = __fsub_rn(cy, hh);
                o2 = __fadd_rn(cx, hw); o3 = __fadd_rn(cy, hh);
                o4 = __uint_as_float((unsigned)(v >> 32));
                o5 = (float)l;
            }
            float* o = out + ((size_t)img * DET + tid) * 6;
            o[0]=o0; o[1]=o1; o[2]=o2; o[3]=o3; o[4]=o4; o[5]=o5;
        }
    } else if (!slow) {
        // kept in (1024, 2048]: smem bitonic over 2048
        for (int i = tid; i < MAXC; i += 1024)
            keys[i] = (i < n) ? g_kept[img][i] : 0ULL;
        __syncthreads();
        bitonic_desc(keys, MAXC, tid, 1024);
        for (int d = tid; d < DET; d += 1024) {
            float o0=0.f,o1=0.f,o2=0.f,o3=0.f,o4=0.f,o5=0.f;
            unsigned long long k = keys[d];
            if (k != 0ULL) {
                unsigned flat = 0xFFFFFFFFu - (unsigned)k;
                int anchor = (int)(flat / NC);
                int l = (int)flat - anchor * NC;
                const float* row = pred + ((size_t)img * NANCH + anchor) * NCH;
                float cx = row[0], cy = row[1], w = row[2], h = row[3];
                float hw = __fmul_rn(0.5f, w), hh = __fmul_rn(0.5f, h);
                o0 = __fsub_rn(cx, hw); o1 = __fsub_rn(cy, hh);
                o2 = __fadd_rn(cx, hw); o3 = __fadd_rn(cy, hh);
                o4 = __uint_as_float((unsigned)(k >> 32));
                o5 = (float)l;
            }
            float* o = out + ((size_t)img * DET + d) * 6;
            o[0]=o0; o[1]=o1; o[2]=o2; o[3]=o3; o[4]=o4; o[5]=o5;
        }
    } else {
        // ---- slow path: full pipeline (statistically never taken) ----
        float4*         rawb  = (float4*)(smem + OFF_RAWB);
        float4*         offb  = (float4*)(smem + OFF_OFFB);
        unsigned char*  lab   = (unsigned char*)(smem + OFF_LAB);
        unsigned char*  keep  = (unsigned char*)(smem + OFF_KEEP);
        unsigned short* clist = (unsigned short*)(smem + OFF_CLIST);
        int*            cnt   = (int*)(smem + OFF_CNT);
        int*            start = (int*)(smem + OFF_START);
        int*            cnt2  = (int*)(smem + OFF_CNT2);
        int*            misc  = (int*)(smem + OFF_MISC);

        const int cload  = min(count, CAPK);
        const int nvalid = min(count, MAXC);
        if (tid < NC) { cnt[tid] = 0; cnt2[tid] = 0; }
        if (tid == 0) misc[0] = 0;
        for (int i = tid; i < CAPK; i += 1024)
            keys[i] = (i < cload) ? g_keys[img][i] : 0ULL;
        bitonic_desc(keys, CAPK, tid, 1024);

        for (int r = tid; r < MAXC; r += 1024) {
            if (r < nvalid) {
                unsigned long long k = keys[r];
                unsigned flat = 0xFFFFFFFFu - (unsigned)k;
                int anchor = (int)(flat / NC);
                int l = (int)flat - anchor * NC;
                const float* row = pred + ((size_t)img * NANCH + anchor) * NCH;
                float cx = row[0], cy = row[1], w = row[2], h = row[3];
                float hw = __fmul_rn(0.5f, w), hh = __fmul_rn(0.5f, h);
                float4 rb;
                rb.x = __fsub_rn(cx, hw); rb.y = __fsub_rn(cy, hh);
                rb.z = __fadd_rn(cx, hw); rb.w = __fadd_rn(cy, hh);
                float off = __fmul_rn((float)l, 4.0f);
                float4 ob;
                ob.x = __fadd_rn(rb.x, off); ob.y = __fadd_rn(rb.y, off);
                ob.z = __fadd_rn(rb.z, off); ob.w = __fadd_rn(rb.w, off);
                rawb[r] = rb; offb[r] = ob;
                lab[r] = (unsigned char)l; keep[r] = 1;
                atomicAdd(&cnt[l], 1);
            } else { lab[r] = 255; keep[r] = 0; }
        }
        __syncthreads();
        if (tid == 0) { int run = 0; for (int l = 0; l < NC; l++) { start[l] = run; run += cnt[l]; } }
        __syncthreads();
        for (int r = tid; r < nvalid; r += 1024) {
            int l = lab[r];
            int p = start[l] + atomicAdd(&cnt2[l], 1);
            clist[p] = (unsigned short)r;
        }
        __syncthreads();

        for (int l = warp; l < NC; l += 32) {
            const int b0 = start[l], kk = cnt[l];
            while (true) {
                unsigned long long bkey = 0ULL; int bidx = -1;
                for (int b = lane; b < kk; b += 32) {
                    int r = clist[b0 + b];
                    if (keep[r] == 1) {
                        unsigned long long kc = keys[r];
                        if (kc > bkey) { bkey = kc; bidx = b; }
                    }
                }
                #pragma unroll
                for (int o = 16; o > 0; o >>= 1) {
                    unsigned long long ok = __shfl_xor_sync(FULLM, bkey, o);
                    int ob = __shfl_xor_sync(FULLM, bidx, o);
                    if (ok > bkey) { bkey = ok; bidx = ob; }
                }
                if (bkey == 0ULL) break;
                int ra = clist[b0 + bidx];
                if (lane == 0) keep[ra] = 2;
                __syncwarp();
                float4 A = offb[ra];
                float areaA = __fmul_rn(__fsub_rn(A.z, A.x), __fsub_rn(A.w, A.y));
                for (int b = lane; b < kk; b += 32) {
                    int r = clist[b0 + b];
                    if (keep[r] == 1 && iou_gt(A, areaA, offb[r])) keep[r] = 0;
                }
                __syncwarp();
            }
        }
        __syncthreads();
        for (int i = tid; i < MAXC; i += 1024) keys[MAXC + i] = 0ULL;
        __syncthreads();
        for (int r = tid; r < nvalid; r += 1024) {
            if (keep[r] == 2) {
                unsigned long long k = keys[r];
                unsigned flat = 0xFFFFFFFFu - (unsigned)k;
                unsigned lo = ((0x1FFFFFu - flat) << 11) | (unsigned)r;
                int p = atomicAdd(&misc[0], 1);
                if (p < MAXC)
                    keys[MAXC + p] = (k & 0xFFFFFFFF00000000ULL) | (unsigned long long)lo;
            }
        }
        __syncthreads();
        int kept_n = min(misc[0], MAXC);
        int m = 1; while (m < kept_n) m <<= 1;
        bitonic_desc(keys + MAXC, m, tid, 1024);
        for (int d = tid; d < DET; d += 1024) {
            float o0=0.f,o1=0.f,o2=0.f,o3=0.f,o4=0.f,o5=0.f;
            unsigned long long k = (d < m) ? keys[MAXC + d] : 0ULL;
            if (k != 0ULL) {
                int r = (int)((unsigned)k & 0x7FFu);
                float4 rb = rawb[r];
                o0 = rb.x; o1 = rb.y; o2 = rb.z; o3 = rb.w;
                o4 = __uint_as_float((unsigned)(k >> 32));
                o5 = (float)lab[r];
            }
            float* o = out + ((size_t)img * DET + d) * 6;
            o[0]=o0; o[1]=o1; o[2]=o2; o[3]=o3; o[4]=o4; o[5]=o5;
        }
    }

    // reset all per-image counters for the next launch / graph replay
    __syncthreads();
    if (tid == 0) { g_count[img] = 0; g_kcnt[img] = 0; g_slow[img] = 0; }
    if (tid < NC) g_bcnt[img * NC + tid] = 0;
}

// ---------------- launch: TWO kernels ----------------
extern "C" void kernel_launch(void* const* d_in, const int* in_sizes, int n_in,
                              void* d_out, int out_size) {
    const float* pred = (const float*)d_in[0];
    float* out = (float*)d_out;

    cudaFuncSetAttribute(k_cf, cudaFuncAttributeMaxDynamicSharedMemorySize, SMEM_TOTAL);

    dim3 g1((NANCH + 255) / 256, NIMG);
    k_extract<<<g1, 256>>>(pred);
    k_cf<<<CF_GRID, 1024, SMEM_TOTAL>>>(pred, out);
    (void)in_sizes; (void)n_in; (void)out_size;
}

// round 15
// speedup vs baseline: 1.3179x; 1.3179x over previous
#include <cuda_runtime.h>
#include <cstdint>

#define NIMG   8
#define NANCH  25200
#define NCH    85
#define NC     80
#define MAXC   2048
#define CAPK   4096
#define BCAP   64
#define DET    300
#define CONF   0.96f
#define IOUT   0.45f
#define FULLM  0xffffffffu

#define FINAL_GRID 148

// ---------------- device scratch (no allocations allowed) ----------------
__device__ int g_count[NIMG];
__device__ int g_bcnt[NIMG * NC];
__device__ int g_kcnt[NIMG];
__device__ int g_slow[NIMG];
__device__ unsigned long long g_keys[NIMG][CAPK];
__device__ unsigned long long g_bucket[NIMG * NC][BCAP];
__device__ unsigned long long g_kept[NIMG][MAXC];

// ---------------- K1: candidate extraction ----------------
// 400 blocks x 256 thr (single wave at 5 blocks/SM). Each warp owns 64 anchors
// via 2 independent obj loads (MLP=2); passing anchors batched 4-at-a-time for
// the row gathers (up to 12 loads in flight).
__global__ void __launch_bounds__(256) k_extract(const float* __restrict__ pred) {
    const int img  = blockIdx.y;
    const int warp = threadIdx.x >> 5;
    const int lane = threadIdx.x & 31;
    const int wbase = blockIdx.x * 512 + warp * 64;   // 64 anchors per warp

    __shared__ unsigned long long sbuf[1024];
    __shared__ int sn, sbase;
    if (threadIdx.x == 0) sn = 0;
    __syncthreads();

    float obj[2];
    #pragma unroll
    for (int j = 0; j < 2; j++) {
        int a = wbase + j * 32 + lane;
        obj[j] = (a < NANCH) ? pred[((size_t)img * NANCH + a) * NCH + 4] : 0.0f;
    }

    #pragma unroll
    for (int j = 0; j < 2; j++) {
        const int abase = wbase + j * 32;
        unsigned mask = __ballot_sync(FULLM, obj[j] > CONF);
        while (mask) {
            bool  val[4]; int aa[4]; float oo[4];
            #pragma unroll
            for (int u = 0; u < 4; u++) {
                val[u] = (mask != 0);
                int i = 0;
                if (mask) { i = __ffs(mask) - 1; mask &= mask - 1; }
                aa[u] = abase + i;
                oo[u] = __shfl_sync(FULLM, obj[j], i);
            }
            float v0[4], v1[4], v2[4];
            #pragma unroll
            for (int u = 0; u < 4; u++) {
                const float* row = pred + ((size_t)img * NANCH + aa[u]) * NCH;
                v0[u] = val[u] ? row[5  + lane] : 0.0f;
                v1[u] = val[u] ? row[37 + lane] : 0.0f;
                v2[u] = (val[u] && lane < 16) ? row[69 + lane] : 0.0f;
            }
            #pragma unroll
            for (int u = 0; u < 4; u++) {
                if (!val[u]) continue;                  // warp-uniform
                #pragma unroll
                for (int cc = 0; cc < 3; cc++) {
                    int c = lane + cc * 32;
                    float v = (cc == 0) ? v0[u] : (cc == 1) ? v1[u] : v2[u];
                    if (c < NC) {
                        float s = __fmul_rn(v, oo[u]);  // matches XLA rn mul
                        if (s > CONF) {
                            unsigned long long key =
                                ((unsigned long long)__float_as_uint(s) << 32) |
                                (unsigned long long)(0xFFFFFFFFu - (unsigned)(aa[u] * NC + c));
                            int bi = img * NC + c;
                            int bp = atomicAdd(&g_bcnt[bi], 1);
                            if (bp < BCAP) g_bucket[bi][bp] = key;
                            int lp = atomicAdd(&sn, 1);
                            if (lp < 1024) sbuf[lp] = key;
                            else {
                                int gp = atomicAdd(&g_count[img], 1);
                                if (gp < CAPK) g_keys[img][gp] = key;
                            }
                        }
                    }
                }
            }
        }
    }
    __syncthreads();
    int n = min(sn, 1024);
    if (threadIdx.x == 0) sbase = atomicAdd(&g_count[img], n);
    __syncthreads();
    for (int i = threadIdx.x; i < n; i += 256) {
        int gp = sbase + i;
        if (gp < CAPK) g_keys[img][gp] = sbuf[i];
    }
}

// ---------------- exact IoU matching the reference fp32 sequence ----------------
__device__ __forceinline__ bool iou_gt(const float4 A, const float areaA, const float4 B) {
    float ltx = fmaxf(A.x, B.x), lty = fmaxf(A.y, B.y);
    float rbx = fminf(A.z, B.z), rby = fminf(A.w, B.w);
    float wx = fmaxf(__fsub_rn(rbx, ltx), 0.0f);
    float wy = fmaxf(__fsub_rn(rby, lty), 0.0f);
    float inter = __fmul_rn(wx, wy);
    float areaB = __fmul_rn(__fsub_rn(B.z, B.x), __fsub_rn(B.w, B.y));
    float denom = __fadd_rn(__fsub_rn(__fadd_rn(areaA, areaB), inter), 1e-9f);
    return __fdiv_rn(inter, denom) > IOUT;
}

__device__ __forceinline__ unsigned long long cmpswap64(unsigned long long v, int j,
                                                        bool desc, int idx) {
    unsigned long long x = __shfl_xor_sync(FULLM, v, j);
    bool lower = (idx & j) == 0;
    bool takeMax = (lower == desc);
    return takeMax ? (v > x ? v : x) : (v < x ? v : x);
}

__device__ __forceinline__ void decode_off(const float* __restrict__ pred, int img,
                                           unsigned long long key, float4* ob, float* ar) {
    unsigned flat = 0xFFFFFFFFu - (unsigned)key;
    int anchor = (int)(flat / NC);
    int l = (int)flat - anchor * NC;
    const float* row = pred + ((size_t)img * NANCH + anchor) * NCH;
    float cx = row[0], cy = row[1], w = row[2], h = row[3];
    float hw = __fmul_rn(0.5f, w), hh = __fmul_rn(0.5f, h);
    float off = __fmul_rn((float)l, 4.0f);
    ob->x = __fadd_rn(__fsub_rn(cx, hw), off);
    ob->y = __fadd_rn(__fsub_rn(cy, hh), off);
    ob->z = __fadd_rn(__fadd_rn(cx, hw), off);
    ob->w = __fadd_rn(__fadd_rn(cy, hh), off);
    *ar = __fmul_rn(__fsub_rn(ob->z, ob->x), __fsub_rn(ob->w, ob->y));
}

// ---------------- K2: warp-per-(img,class) register NMS (R13-proven) ----------
__global__ void __launch_bounds__(128) k_cls(const float* __restrict__ pred) {
    const int gwarp = blockIdx.x * 4 + (threadIdx.x >> 5);
    if (gwarp >= NIMG * NC) return;
    const int img  = gwarp / NC;
    const int lane = threadIdx.x & 31;

    const int count = g_count[img];
    const int kk = g_bcnt[gwarp];
    if (kk > BCAP) { if (lane == 0) g_slow[img] = 1; return; }
    if (count > MAXC) return;
    if (kk == 0) return;

    if (kk <= 32) {
        unsigned long long v0 = (lane < kk) ? g_bucket[gwarp][lane] : 0ULL;
        #pragma unroll
        for (int k = 2; k <= 32; k <<= 1)
            #pragma unroll
            for (int j = k >> 1; j > 0; j >>= 1)
                v0 = cmpswap64(v0, j, (lane & k) == 0, lane);

        float4 ob0 = make_float4(0.f,0.f,0.f,0.f);
        float ar0 = 0.f;
        if (lane < kk) decode_off(pred, img, v0, &ob0, &ar0);

        unsigned m0 = 0u;
        for (int t = 1; t < kk; t++) {
            float4 B;
            B.x = __shfl_sync(FULLM, ob0.x, t); B.y = __shfl_sync(FULLM, ob0.y, t);
            B.z = __shfl_sync(FULLM, ob0.z, t); B.w = __shfl_sync(FULLM, ob0.w, t);
            if (lane < t && iou_gt(ob0, ar0, B)) m0 |= 1u << t;
        }
        unsigned alive = (kk >= 32) ? 0xFFFFFFFFu : ((1u << kk) - 1u);
        for (int t = 0; t < kk; t++) {
            unsigned mt = __shfl_sync(FULLM, m0, t);
            if ((alive >> t) & 1u) alive &= ~mt;
        }
        bool k0 = (lane < kk) && ((alive >> lane) & 1u);
        unsigned b0 = __ballot_sync(FULLM, k0);
        int tot = __popc(b0);
        int base = 0;
        if (lane == 0 && tot) base = atomicAdd(&g_kcnt[img], tot);
        base = __shfl_sync(FULLM, base, 0);
        if (k0) {
            int p = base + __popc(b0 & ((1u << lane) - 1u));
            if (p < MAXC) g_kept[img][p] = v0;
        }
        return;
    }

    // ---------- 64-wide path (rare) ----------
    unsigned long long v0 = (lane      < kk) ? g_bucket[gwarp][lane]      : 0ULL;
    unsigned long long v1 = (lane + 32 < kk) ? g_bucket[gwarp][lane + 32] : 0ULL;

    #pragma unroll
    for (int k = 2; k <= 64; k <<= 1) {
        #pragma unroll
        for (int j = k >> 1; j > 0; j >>= 1) {
            if (j >= 32) {
                unsigned long long a = v0 > v1 ? v0 : v1;
                unsigned long long b = v0 > v1 ? v1 : v0;
                v0 = a; v1 = b;
            } else {
                v0 = cmpswap64(v0, j, ((lane       & k) == 0), lane);
                v1 = cmpswap64(v1, j, (((lane + 32) & k) == 0), lane);
            }
        }
    }

    float4 ob0 = make_float4(0.f,0.f,0.f,0.f), ob1 = ob0;
    float ar0 = 0.f, ar1 = 0.f;
    if (lane      < kk) decode_off(pred, img, v0, &ob0, &ar0);
    if (lane + 32 < kk) decode_off(pred, img, v1, &ob1, &ar1);

    unsigned long long m0 = 0ULL, m1 = 0ULL;
    for (int t = 0; t < kk; t++) {
        int sl = t & 31;
        float4 B;
        if (t >= 32) {
            B.x = __shfl_sync(FULLM, ob1.x, sl); B.y = __shfl_sync(FULLM, ob1.y, sl);
            B.z = __shfl_sync(FULLM, ob1.z, sl); B.w = __shfl_sync(FULLM, ob1.w, sl);
        } else {
            B.x = __shfl_sync(FULLM, ob0.x, sl); B.y = __shfl_sync(FULLM, ob0.y, sl);
            B.z = __shfl_sync(FULLM, ob0.z, sl); B.w = __shfl_sync(FULLM, ob0.w, sl);
        }
        if (lane < t && lane < kk && iou_gt(ob0, ar0, B)) m0 |= 1ULL << t;
        if (lane + 32 < t && iou_gt(ob1, ar1, B))         m1 |= 1ULL << t;
    }

    unsigned long long alive = (kk >= 64) ? ~0ULL : ((1ULL << kk) - 1ULL);
    for (int t = 0; t < kk; t++) {
        unsigned long long mt = __shfl_sync(FULLM, (t >= 32) ? m1 : m0, t & 31);
        if ((alive >> t) & 1ULL) alive &= ~mt;
    }

    bool k0 = (lane      < kk) && ((alive >> lane) & 1ULL);
    bool k1 = (lane + 32 < kk) && ((alive >> (lane + 32)) & 1ULL);
    unsigned b0 = __ballot_sync(FULLM, k0);
    unsigned b1 = __ballot_sync(FULLM, k1);
    int tot = __popc(b0) + __popc(b1);
    int base = 0;
    if (lane == 0 && tot) base = atomicAdd(&g_kcnt[img], tot);
    base = __shfl_sync(FULLM, base, 0);
    unsigned lt = (1u << lane) - 1u;
    if (k0) { int p = base + __popc(b0 & lt);              if (p < MAXC) g_kept[img][p] = v0; }
    if (k1) { int p = base + __popc(b0) + __popc(b1 & lt); if (p < MAXC) g_kept[img][p] = v1; }
}

// ---------------- block bitonic (descending, smem) ----------------
__device__ __forceinline__ void bitonic_desc(unsigned long long* a, int n, int tid, int nthreads) {
    for (int k = 2; k <= n; k <<= 1) {
        for (int j = k >> 1; j > 0; j >>= 1) {
            __syncthreads();
            for (int i = tid; i < n; i += nthreads) {
                int p = i ^ j;
                if (p > i) {
                    bool up = (i & k) == 0;
                    unsigned long long x = a[i], y = a[p];
                    bool sw = up ? (x < y) : (x > y);
                    if (sw) { a[i] = y; a[p] = x; }
                }
            }
        }
    }
    __syncthreads();
}

// ---------------- smem layout (sized for the slow path) ----------------
#define OFF_KEYS   0        // u64[4096]
#define OFF_RAWB   32768    // float4[2048]
#define OFF_OFFB   65536    // float4[2048]
#define OFF_LAB    98304    // u8[2048]
#define OFF_KEEP   100352   // u8[2048]
#define OFF_CLIST  102400   // u16[2048]
#define OFF_CNT    106496   // int[80]
#define OFF_START  106816   // int[80]
#define OFF_CNT2   107136   // int[80]
#define OFF_MISC   107456   // int[16]
#define SMEM_TOTAL 107520

// ---------------- K3: per-image final sort + emit (R13-proven) ---------------
__global__ void __launch_bounds__(1024, 1) k_final(const float* __restrict__ pred,
                                                   float* __restrict__ out) {
    const int img = blockIdx.x;
    if (img >= NIMG) return;

    extern __shared__ unsigned char smem[];
    unsigned long long* keys = (unsigned long long*)(smem + OFF_KEYS);

    const int tid = threadIdx.x;
    const int count = g_count[img];
    const bool slow = (count > MAXC) || (g_slow[img] != 0);
    const int n = min(g_kcnt[img], MAXC);

    if (!slow && n <= 1024) {
        unsigned long long v = (tid < n) ? g_kept[img][tid] : 0ULL;
        unsigned long long* b0 = keys;
        unsigned long long* b1 = keys + 1024;
        int pp = 0;
        #pragma unroll
        for (int k = 2; k <= 1024; k <<= 1) {
            int j = k >> 1;
            for (; j >= 32; j >>= 1) {
                unsigned long long* buf = pp ? b1 : b0; pp ^= 1;
                buf[tid] = v;
                __syncthreads();
                unsigned long long x = buf[tid ^ j];
                bool lower = (tid & j) == 0;
                bool desc  = (tid & k) == 0;
                bool takeMax = (lower == desc);
                v = takeMax ? (v > x ? v : x) : (v < x ? v : x);
            }
            for (; j > 0; j >>= 1)
                v = cmpswap64(v, j, (tid & k) == 0, tid);
        }
        if (tid < DET) {
            float o0=0.f,o1=0.f,o2=0.f,o3=0.f,o4=0.f,o5=0.f;
            if (v != 0ULL) {
                unsigned flat = 0xFFFFFFFFu - (unsigned)v;
                int anchor = (int)(flat / NC);
                int l = (int)flat - anchor * NC;
                const float* row = pred + ((size_t)img * NANCH + anchor) * NCH;
                float cx = row[0], cy = row[1], w = row[2], h = row[3];
                float hw = __fmul_rn(0.5f, w), hh = __fmul_rn(0.5f, h);
                o0 = __fsub_rn(cx, hw); o1 = __fsub_rn(cy, hh);
                o2 = __fadd_rn(cx, hw); o3 = __fadd_rn(cy, hh);
                o4 = __uint_as_float((unsigned)(v >> 32));
                o5 = (float)l;
            }
            float* o = out + ((size_t)img * DET + tid) * 6;
            o[0]=o0; o[1]=o1; o[2]=o2; o[3]=o3; o[4]=o4; o[5]=o5;
        }
    } else if (!slow) {
        for (int i = tid; i < MAXC; i += 1024)
            keys[i] = (i < n) ? g_kept[img][i] : 0ULL;
        __syncthreads();
        bitonic_desc(keys, MAXC, tid, 1024);
        for (int d = tid; d < DET; d += 1024) {
            float o0=0.f,o1=0.f,o2=0.f,o3=0.f,o4=0.f,o5=0.f;
            unsigned long long k = keys[d];
            if (k != 0ULL) {
                unsigned flat = 0xFFFFFFFFu - (unsigned)k;
                int anchor = (int)(flat / NC);
                int l = (int)flat - anchor * NC;
                const float* row = pred + ((size_t)img * NANCH + anchor) * NCH;
                float cx = row[0], cy = row[1], w = row[2], h = row[3];
                float hw = __fmul_rn(0.5f, w), hh = __fmul_rn(0.5f, h);
                o0 = __fsub_rn(cx, hw); o1 = __fsub_rn(cy, hh);
                o2 = __fadd_rn(cx, hw); o3 = __fadd_rn(cy, hh);
                o4 = __uint_as_float((unsigned)(k >> 32));
                o5 = (float)l;
            }
            float* o = out + ((size_t)img * DET + d) * 6;
            o[0]=o0; o[1]=o1; o[2]=o2; o[3]=o3; o[4]=o4; o[5]=o5;
        }
    } else {
        // ---- slow path: full pipeline (statistically never taken) ----
        float4*         rawb  = (float4*)(smem + OFF_RAWB);
        float4*         offb  = (float4*)(smem + OFF_OFFB);
        unsigned char*  lab   = (unsigned char*)(smem + OFF_LAB);
        unsigned char*  keep  = (unsigned char*)(smem + OFF_KEEP);
        unsigned short* clist = (unsigned short*)(smem + OFF_CLIST);
        int*            cnt   = (int*)(smem + OFF_CNT);
        int*            start = (int*)(smem + OFF_START);
        int*            cnt2  = (int*)(smem + OFF_CNT2);
        int*            misc  = (int*)(smem + OFF_MISC);

        const int cload  = min(count, CAPK);
        const int nvalid = min(count, MAXC);
        if (tid < NC) { cnt[tid] = 0; cnt2[tid] = 0; }
        if (tid == 0) misc[0] = 0;
        for (int i = tid; i < CAPK; i += 1024)
            keys[i] = (i < cload) ? g_keys[img][i] : 0ULL;
        bitonic_desc(keys, CAPK, tid, 1024);

        for (int r = tid; r < MAXC; r += 1024) {
            if (r < nvalid) {
                unsigned long long k = keys[r];
                unsigned flat = 0xFFFFFFFFu - (unsigned)k;
                int anchor = (int)(flat / NC);
                int l = (int)flat - anchor * NC;
                const float* row = pred + ((size_t)img * NANCH + anchor) * NCH;
                float cx = row[0], cy = row[1], w = row[2], h = row[3];
                float hw = __fmul_rn(0.5f, w), hh = __fmul_rn(0.5f, h);
                float4 rb;
                rb.x = __fsub_rn(cx, hw); rb.y = __fsub_rn(cy, hh);
                rb.z = __fadd_rn(cx, hw); rb.w = __fadd_rn(cy, hh);
                float off = __fmul_rn((float)l, 4.0f);
                float4 ob;
                ob.x = __fadd_rn(rb.x, off); ob.y = __fadd_rn(rb.y, off);
                ob.z = __fadd_rn(rb.z, off); ob.w = __fadd_rn(rb.w, off);
                rawb[r] = rb; offb[r] = ob;
                lab[r] = (unsigned char)l; keep[r] = 1;
                atomicAdd(&cnt[l], 1);
            } else { lab[r] = 255; keep[r] = 0; }
        }
        __syncthreads();
        if (tid == 0) { int run = 0; for (int l = 0; l < NC; l++) { start[l] = run; run += cnt[l]; } }
        __syncthreads();
        for (int r = tid; r < nvalid; r += 1024) {
            int l = lab[r];
            int p = start[l] + atomicAdd(&cnt2[l], 1);
            clist[p] = (unsigned short)r;
        }
        __syncthreads();

        const int warp = tid >> 5, lane = tid & 31;
        for (int l = warp; l < NC; l += 32) {
            const int b0 = start[l], kk = cnt[l];
            while (true) {
                unsigned long long bkey = 0ULL; int bidx = -1;
                for (int b = lane; b < kk; b += 32) {
                    int r = clist[b0 + b];
                    if (keep[r] == 1) {
                        unsigned long long kc = keys[r];
                        if (kc > bkey) { bkey = kc; bidx = b; }
                    }
                }
                #pragma unroll
                for (int o = 16; o > 0; o >>= 1) {
                    unsigned long long ok = __shfl_xor_sync(FULLM, bkey, o);
                    int ob = __shfl_xor_sync(FULLM, bidx, o);
                    if (ok > bkey) { bkey = ok; bidx = ob; }
                }
                if (bkey == 0ULL) break;
                int ra = clist[b0 + bidx];
                if (lane == 0) keep[ra] = 2;
                __syncwarp();
                float4 A = offb[ra];
                float areaA = __fmul_rn(__fsub_rn(A.z, A.x), __fsub_rn(A.w, A.y));
                for (int b = lane; b < kk; b += 32) {
                    int r = clist[b0 + b];
                    if (keep[r] == 1 && iou_gt(A, areaA, offb[r])) keep[r] = 0;
                }
                __syncwarp();
            }
        }
        __syncthreads();
        for (int i = tid; i < MAXC; i += 1024) keys[MAXC + i] = 0ULL;
        __syncthreads();
        for (int r = tid; r < nvalid; r += 1024) {
            if (keep[r] == 2) {
                unsigned long long k = keys[r];
                unsigned flat = 0xFFFFFFFFu - (unsigned)k;
                unsigned lo = ((0x1FFFFFu - flat) << 11) | (unsigned)r;
                int p = atomicAdd(&misc[0], 1);
                if (p < MAXC)
                    keys[MAXC + p] = (k & 0xFFFFFFFF00000000ULL) | (unsigned long long)lo;
            }
        }
        __syncthreads();
        int kept_n = min(misc[0], MAXC);
        int m = 1; while (m < kept_n) m <<= 1;
        bitonic_desc(keys + MAXC, m, tid, 1024);
        for (int d = tid; d < DET; d += 1024) {
            float o0=0.f,o1=0.f,o2=0.f,o3=0.f,o4=0.f,o5=0.f;
            unsigned long long k = (d < m) ? keys[MAXC + d] : 0ULL;
            if (k != 0ULL) {
                int r = (int)((unsigned)k & 0x7FFu);
                float4 rb = rawb[r];
                o0 = rb.x; o1 = rb.y; o2 = rb.z; o3 = rb.w;
                o4 = __uint_as_float((unsigned)(k >> 32));
                o5 = (float)lab[r];
            }
            float* o = out + ((size_t)img * DET + d) * 6;
            o[0]=o0; o[1]=o1; o[2]=o2; o[3]=o3; o[4]=o4; o[5]=o5;
        }
    }

    // reset all per-image counters for the next launch / graph replay
    __syncthreads();
    if (tid == 0) { g_count[img] = 0; g_kcnt[img] = 0; g_slow[img] = 0; }
    if (tid < NC) g_bcnt[img * NC + tid] = 0;
}

// ---------------- launch ----------------
extern "C" void kernel_launch(void* const* d_in, const int* in_sizes, int n_in,
                              void* d_out, int out_size) {
    const float* pred = (const float*)d_in[0];
    float* out = (float*)d_out;

    cudaFuncSetAttribute(k_final, cudaFuncAttributeMaxDynamicSharedMemorySize, SMEM_TOTAL);

    dim3 g1((NANCH + 511) / 512, NIMG);   // 50 x 8 = 400 blocks, single wave
    k_extract<<<g1, 256>>>(pred);
    k_cls<<<(NIMG * NC + 3) / 4, 128>>>(pred);
    k_final<<<FINAL_GRID, 1024, SMEM_TOTAL>>>(pred, out);
    (void)in_sizes; (void)n_in; (void)out_size;
}

// round 17
// speedup vs baseline: 1.6648x; 1.2632x over previous
#include <cuda_runtime.h>
#include <cstdint>

#define NIMG   8
#define NANCH  25200
#define NCH    85
#define NC     80
#define MAXC   2048
#define CAPK   4096
#define BCAP   64
#define DET    300
#define CONF   0.96f
#define IOUT   0.45f
#define FULLM  0xffffffffu

#define FINAL_GRID 148

// ---------------- device scratch (no allocations allowed) ----------------
__device__ int g_count[NIMG];
__device__ int g_bcnt[NIMG * NC];
__device__ int g_kcnt[NIMG];
__device__ int g_slow[NIMG];
__device__ unsigned long long g_keys[NIMG][CAPK];
__device__ unsigned long long g_bucket[NIMG * NC][BCAP];
__device__ unsigned long long g_kept[NIMG][MAXC];

// ---------------- K1: candidate extraction (R13-proven geometry) -------------
__global__ void __launch_bounds__(256) k_extract(const float* __restrict__ pred) {
    const int img  = blockIdx.y;
    const int warp = threadIdx.x >> 5;
    const int lane = threadIdx.x & 31;
    const int abase = blockIdx.x * 256 + warp * 32;

    __shared__ unsigned long long sbuf[1024];
    __shared__ int sn, sbase;
    if (threadIdx.x == 0) sn = 0;
    __syncthreads();

    int a = abase + lane;
    float obj = 0.0f;
    if (a < NANCH) obj = pred[((size_t)img * NANCH + a) * NCH + 4];

    unsigned mask = __ballot_sync(FULLM, obj > CONF);
    while (mask) {
        bool  val[4]; int aa[4]; float oo[4];
        #pragma unroll
        for (int u = 0; u < 4; u++) {
            val[u] = (mask != 0);
            int i = 0;
            if (mask) { i = __ffs(mask) - 1; mask &= mask - 1; }
            aa[u] = abase + i;
            oo[u] = __shfl_sync(FULLM, obj, i);
        }
        float v0[4], v1[4], v2[4];
        #pragma unroll
        for (int u = 0; u < 4; u++) {
            const float* row = pred + ((size_t)img * NANCH + aa[u]) * NCH;
            v0[u] = val[u] ? row[5  + lane] : 0.0f;
            v1[u] = val[u] ? row[37 + lane] : 0.0f;
            v2[u] = (val[u] && lane < 16) ? row[69 + lane] : 0.0f;
        }
        #pragma unroll
        for (int u = 0; u < 4; u++) {
            if (!val[u]) continue;                      // warp-uniform
            #pragma unroll
            for (int cc = 0; cc < 3; cc++) {
                int c = lane + cc * 32;
                float v = (cc == 0) ? v0[u] : (cc == 1) ? v1[u] : v2[u];
                if (c < NC) {
                    float s = __fmul_rn(v, oo[u]);      // matches XLA rn mul
                    if (s > CONF) {
                        unsigned long long key =
                            ((unsigned long long)__float_as_uint(s) << 32) |
                            (unsigned long long)(0xFFFFFFFFu - (unsigned)(aa[u] * NC + c));
                        int bi = img * NC + c;
                        int bp = atomicAdd(&g_bcnt[bi], 1);
                        if (bp < BCAP) g_bucket[bi][bp] = key;
                        int lp = atomicAdd(&sn, 1);
                        if (lp < 1024) sbuf[lp] = key;
                        else {
                            int gp = atomicAdd(&g_count[img], 1);
                            if (gp < CAPK) g_keys[img][gp] = key;
                        }
                    }
                }
            }
        }
    }
    __syncthreads();
    int n = min(sn, 1024);
    if (threadIdx.x == 0) sbase = atomicAdd(&g_count[img], n);
    __syncthreads();
    for (int i = threadIdx.x; i < n; i += 256) {
        int gp = sbase + i;
        if (gp < CAPK) g_keys[img][gp] = sbuf[i];
    }
}

// ---------------- exact IoU matching the reference fp32 sequence ----------------
__device__ __forceinline__ bool iou_gt(const float4 A, const float areaA, const float4 B) {
    float ltx = fmaxf(A.x, B.x), lty = fmaxf(A.y, B.y);
    float rbx = fminf(A.z, B.z), rby = fminf(A.w, B.w);
    float wx = fmaxf(__fsub_rn(rbx, ltx), 0.0f);
    float wy = fmaxf(__fsub_rn(rby, lty), 0.0f);
    float inter = __fmul_rn(wx, wy);
    float areaB = __fmul_rn(__fsub_rn(B.z, B.x), __fsub_rn(B.w, B.y));
    float denom = __fadd_rn(__fsub_rn(__fadd_rn(areaA, areaB), inter), 1e-9f);
    return __fdiv_rn(inter, denom) > IOUT;
}

__device__ __forceinline__ unsigned long long cmpswap64(unsigned long long v, int j,
                                                        bool desc, int idx) {
    unsigned long long x = __shfl_xor_sync(FULLM, v, j);
    bool lower = (idx & j) == 0;
    bool takeMax = (lower == desc);
    return takeMax ? (v > x ? v : x) : (v < x ? v : x);
}

__device__ __forceinline__ void decode_off(const float* __restrict__ pred, int img,
                                           unsigned long long key, float4* ob, float* ar) {
    unsigned flat = 0xFFFFFFFFu - (unsigned)key;
    int anchor = (int)(flat / NC);
    int l = (int)flat - anchor * NC;
    const float* row = pred + ((size_t)img * NANCH + anchor) * NCH;
    float cx = row[0], cy = row[1], w = row[2], h = row[3];
    float hw = __fmul_rn(0.5f, w), hh = __fmul_rn(0.5f, h);
    float off = __fmul_rn((float)l, 4.0f);
    ob->x = __fadd_rn(__fsub_rn(cx, hw), off);
    ob->y = __fadd_rn(__fsub_rn(cy, hh), off);
    ob->z = __fadd_rn(__fadd_rn(cx, hw), off);
    ob->w = __fadd_rn(__fadd_rn(cy, hh), off);
    *ar = __fmul_rn(__fsub_rn(ob->z, ob->x), __fsub_rn(ob->w, ob->y));
}

// ---------------- K2: warp-per-(img,class) register NMS (R13-proven) ----------
__global__ void __launch_bounds__(128) k_cls(const float* __restrict__ pred) {
    const int gwarp = blockIdx.x * 4 + (threadIdx.x >> 5);
    if (gwarp >= NIMG * NC) return;
    const int img  = gwarp / NC;
    const int lane = threadIdx.x & 31;

    const int count = g_count[img];
    const int kk = g_bcnt[gwarp];
    if (kk > BCAP) { if (lane == 0) g_slow[img] = 1; return; }
    if (count > MAXC) return;
    if (kk == 0) return;

    if (kk <= 32) {
        unsigned long long v0 = (lane < kk) ? g_bucket[gwarp][lane] : 0ULL;
        #pragma unroll
        for (int k = 2; k <= 32; k <<= 1)
            #pragma unroll
            for (int j = k >> 1; j > 0; j >>= 1)
                v0 = cmpswap64(v0, j, (lane & k) == 0, lane);

        float4 ob0 = make_float4(0.f,0.f,0.f,0.f);
        float ar0 = 0.f;
        if (lane < kk) decode_off(pred, img, v0, &ob0, &ar0);

        unsigned m0 = 0u;
        for (int t = 1; t < kk; t++) {
            float4 B;
            B.x = __shfl_sync(FULLM, ob0.x, t); B.y = __shfl_sync(FULLM, ob0.y, t);
            B.z = __shfl_sync(FULLM, ob0.z, t); B.w = __shfl_sync(FULLM, ob0.w, t);
            if (lane < t && iou_gt(ob0, ar0, B)) m0 |= 1u << t;
        }
        unsigned alive = (kk >= 32) ? 0xFFFFFFFFu : ((1u << kk) - 1u);
        for (int t = 0; t < kk; t++) {
            unsigned mt = __shfl_sync(FULLM, m0, t);
            if ((alive >> t) & 1u) alive &= ~mt;
        }
        bool k0 = (lane < kk) && ((alive >> lane) & 1u);
        unsigned b0 = __ballot_sync(FULLM, k0);
        int tot = __popc(b0);
        int base = 0;
        if (lane == 0 && tot) base = atomicAdd(&g_kcnt[img], tot);
        base = __shfl_sync(FULLM, base, 0);
        if (k0) {
            int p = base + __popc(b0 & ((1u << lane) - 1u));
            if (p < MAXC) g_kept[img][p] = v0;
        }
        return;
    }

    // ---------- 64-wide path (rare) ----------
    unsigned long long v0 = (lane      < kk) ? g_bucket[gwarp][lane]      : 0ULL;
    unsigned long long v1 = (lane + 32 < kk) ? g_bucket[gwarp][lane + 32] : 0ULL;

    #pragma unroll
    for (int k = 2; k <= 64; k <<= 1) {
        #pragma unroll
        for (int j = k >> 1; j > 0; j >>= 1) {
            if (j >= 32) {
                unsigned long long a = v0 > v1 ? v0 : v1;
                unsigned long long b = v0 > v1 ? v1 : v0;
                v0 = a; v1 = b;
            } else {
                v0 = cmpswap64(v0, j, ((lane       & k) == 0), lane);
                v1 = cmpswap64(v1, j, (((lane + 32) & k) == 0), lane);
            }
        }
    }

    float4 ob0 = make_float4(0.f,0.f,0.f,0.f), ob1 = ob0;
    float ar0 = 0.f, ar1 = 0.f;
    if (lane      < kk) decode_off(pred, img, v0, &ob0, &ar0);
    if (lane + 32 < kk) decode_off(pred, img, v1, &ob1, &ar1);

    unsigned long long m0 = 0ULL, m1 = 0ULL;
    for (int t = 0; t < kk; t++) {
        int sl = t & 31;
        float4 B;
        if (t >= 32) {
            B.x = __shfl_sync(FULLM, ob1.x, sl); B.y = __shfl_sync(FULLM, ob1.y, sl);
            B.z = __shfl_sync(FULLM, ob1.z, sl); B.w = __shfl_sync(FULLM, ob1.w, sl);
        } else {
            B.x = __shfl_sync(FULLM, ob0.x, sl); B.y = __shfl_sync(FULLM, ob0.y, sl);
            B.z = __shfl_sync(FULLM, ob0.z, sl); B.w = __shfl_sync(FULLM, ob0.w, sl);
        }
        if (lane < t && lane < kk && iou_gt(ob0, ar0, B)) m0 |= 1ULL << t;
        if (lane + 32 < t && iou_gt(ob1, ar1, B))         m1 |= 1ULL << t;
    }

    unsigned long long alive = (kk >= 64) ? ~0ULL : ((1ULL << kk) - 1ULL);
    for (int t = 0; t < kk; t++) {
        unsigned long long mt = __shfl_sync(FULLM, (t >= 32) ? m1 : m0, t & 31);
        if ((alive >> t) & 1ULL) alive &= ~mt;
    }

    bool k0 = (lane      < kk) && ((alive >> lane) & 1ULL);
    bool k1 = (lane + 32 < kk) && ((alive >> (lane + 32)) & 1ULL);
    unsigned b0 = __ballot_sync(FULLM, k0);
    unsigned b1 = __ballot_sync(FULLM, k1);
    int tot = __popc(b0) + __popc(b1);
    int base = 0;
    if (lane == 0 && tot) base = atomicAdd(&g_kcnt[img], tot);
    base = __shfl_sync(FULLM, base, 0);
    unsigned lt = (1u << lane) - 1u;
    if (k0) { int p = base + __popc(b0 & lt);              if (p < MAXC) g_kept[img][p] = v0; }
    if (k1) { int p = base + __popc(b0) + __popc(b1 & lt); if (p < MAXC) g_kept[img][p] = v1; }
}

// ---------------- block bitonic (descending, smem; slow path only) -----------
__device__ __forceinline__ void bitonic_desc(unsigned long long* a, int n, int tid, int nthreads) {
    for (int k = 2; k <= n; k <<= 1) {
        for (int j = k >> 1; j > 0; j >>= 1) {
            __syncthreads();
            for (int i = tid; i < n; i += nthreads) {
                int p = i ^ j;
                if (p > i) {
                    bool up = (i & k) == 0;
                    unsigned long long x = a[i], y = a[p];
                    bool sw = up ? (x < y) : (x > y);
                    if (sw) { a[i] = y; a[p] = x; }
                }
            }
        }
    }
    __syncthreads();
}

// ---------------- smem layout (sized for the slow path) ----------------
#define OFF_KEYS   0        // u64[4096]
#define OFF_RAWB   32768    // float4[2048]
#define OFF_OFFB   65536    // float4[2048]
#define OFF_LAB    98304    // u8[2048]
#define OFF_KEEP   100352   // u8[2048]
#define OFF_CLIST  102400   // u16[2048]
#define OFF_CNT    106496   // int[80]
#define OFF_START  106816   // int[80]
#define OFF_CNT2   107136   // int[80]
#define OFF_MISC   107456   // int[16]
#define SMEM_TOTAL 107520

// ---------------- K3: per-image final sort + emit ----------------
__global__ void __launch_bounds__(1024, 1) k_final(const float* __restrict__ pred,
                                                   float* __restrict__ out) {
    const int img = blockIdx.x;
    if (img >= NIMG) return;

    extern __shared__ unsigned char smem[];
    unsigned long long* keys = (unsigned long long*)(smem + OFF_KEYS);

    const int tid = threadIdx.x;
    const int count = g_count[img];
    const bool slow = (count > MAXC) || (g_slow[img] != 0);
    const int n = min(g_kcnt[img], MAXC);

    if (!slow && n <= 1024) {
        // ---- fast path A: 1 elem/thread hybrid bitonic over 1024 ----
        unsigned long long v = (tid < n) ? g_kept[img][tid] : 0ULL;
        unsigned long long* p0 = keys;
        unsigned long long* p1 = keys + 1024;
        int pp = 0;
        #pragma unroll
        for (int k = 2; k <= 1024; k <<= 1) {
            int j = k >> 1;
            for (; j >= 32; j >>= 1) {
                unsigned long long* buf = pp ? p1 : p0; pp ^= 1;
                buf[tid] = v;
                __syncthreads();
                unsigned long long x = buf[tid ^ j];
                bool lower = (tid & j) == 0;
                bool desc  = (tid & k) == 0;
                v = (lower == desc) ? (v > x ? v : x) : (v < x ? v : x);
            }
            for (; j > 0; j >>= 1)
                v = cmpswap64(v, j, (tid & k) == 0, tid);
        }
        if (tid < DET) {
            float o0=0.f,o1=0.f,o2=0.f,o3=0.f,o4=0.f,o5=0.f;
            if (v != 0ULL) {
                unsigned flat = 0xFFFFFFFFu - (unsigned)v;
                int anchor = (int)(flat / NC);
                int l = (int)flat - anchor * NC;
                const float* row = pred + ((size_t)img * NANCH + anchor) * NCH;
                float cx = row[0], cy = row[1], w = row[2], h = row[3];
                float hw = __fmul_rn(0.5f, w), hh = __fmul_rn(0.5f, h);
                o0 = __fsub_rn(cx, hw); o1 = __fsub_rn(cy, hh);
                o2 = __fadd_rn(cx, hw); o3 = __fadd_rn(cy, hh);
                o4 = __uint_as_float((unsigned)(v >> 32));
                o5 = (float)l;
            }
            float* o = out + ((size_t)img * DET + tid) * 6;
            o[0]=o0; o[1]=o1; o[2]=o2; o[3]=o3; o[4]=o4; o[5]=o5;
        }
    } else if (!slow) {
        // ---- fast path B (common case): 2 elems/thread hybrid bitonic over 2048
        unsigned long long v0 = (tid        < n) ? g_kept[img][tid]        : 0ULL;
        unsigned long long v1 = (tid + 1024 < n) ? g_kept[img][tid + 1024] : 0ULL;
        unsigned long long* p0 = keys;            // 2048 u64
        unsigned long long* p1 = keys + 2048;     // 2048 u64
        int pp = 0;
        #pragma unroll
        for (int k = 2; k <= 2048; k <<= 1) {
            int j = k >> 1;
            if (j >= 1024) {
                // k=2048, j=1024: partner of i0=tid is i1=tid+1024 (in-thread);
                // desc=(i&2048)==0 true for both halves -> v0=max, v1=min
                unsigned long long a = v0 > v1 ? v0 : v1;
                unsigned long long b = v0 > v1 ? v1 : v0;
                v0 = a; v1 = b;
                j >>= 1;
            }
            for (; j >= 32; j >>= 1) {
                unsigned long long* buf = pp ? p1 : p0; pp ^= 1;
                buf[tid] = v0; buf[tid + 1024] = v1;
                __syncthreads();
                unsigned long long x0 = buf[tid ^ j];
                unsigned long long x1 = buf[(tid ^ j) + 1024];
                bool lower = (tid & j) == 0;          // same for i0 and i1 (j<1024)
                bool desc0 = ((tid        & k) == 0);
                bool desc1 = (((tid + 1024) & k) == 0);
                v0 = (lower == desc0) ? (v0 > x0 ? v0 : x0) : (v0 < x0 ? v0 : x0);
                v1 = (lower == desc1) ? (v1 > x1 ? v1 : x1) : (v1 < x1 ? v1 : x1);
            }
            for (; j > 0; j >>= 1) {
                v0 = cmpswap64(v0, j, ((tid        & k) == 0), tid);
                v1 = cmpswap64(v1, j, (((tid + 1024) & k) == 0), tid);
            }
        }
        // element d (d < 1024) lives in thread d register v0
        if (tid < DET) {
            float o0=0.f,o1=0.f,o2=0.f,o3=0.f,o4=0.f,o5=0.f;
            if (v0 != 0ULL) {
                unsigned flat = 0xFFFFFFFFu - (unsigned)v0;
                int anchor = (int)(flat / NC);
                int l = (int)flat - anchor * NC;
                const float* row = pred + ((size_t)img * NANCH + anchor) * NCH;
                float cx = row[0], cy = row[1], w = row[2], h = row[3];
                float hw = __fmul_rn(0.5f, w), hh = __fmul_rn(0.5f, h);
                o0 = __fsub_rn(cx, hw); o1 = __fsub_rn(cy, hh);
                o2 = __fadd_rn(cx, hw); o3 = __fadd_rn(cy, hh);
                o4 = __uint_as_float((unsigned)(v0 >> 32));
                o5 = (float)l;
            }
            float* o = out + ((size_t)img * DET + tid) * 6;
            o[0]=o0; o[1]=o1; o[2]=o2; o[3]=o3; o[4]=o4; o[5]=o5;
        }
    } else {
        // ---- slow path: full pipeline (statistically never taken) ----
        float4*         rawb  = (float4*)(smem + OFF_RAWB);
        float4*         offb  = (float4*)(smem + OFF_OFFB);
        unsigned char*  lab   = (unsigned char*)(smem + OFF_LAB);
        unsigned char*  keep  = (unsigned char*)(smem + OFF_KEEP);
        unsigned short* clist = (unsigned short*)(smem + OFF_CLIST);
        int*            cnt   = (int*)(smem + OFF_CNT);
        int*            start = (int*)(smem + OFF_START);
        int*            cnt2  = (int*)(smem + OFF_CNT2);
        int*            misc  = (int*)(smem + OFF_MISC);

        const int cload  = min(count, CAPK);
        const int nvalid = min(count, MAXC);
        if (tid < NC) { cnt[tid] = 0; cnt2[tid] = 0; }
        if (tid == 0) misc[0] = 0;
        for (int i = tid; i < CAPK; i += 1024)
            keys[i] = (i < cload) ? g_keys[img][i] : 0ULL;
        bitonic_desc(keys, CAPK, tid, 1024);

        for (int r = tid; r < MAXC; r += 1024) {
            if (r < nvalid) {
                unsigned long long k = keys[r];
                unsigned flat = 0xFFFFFFFFu - (unsigned)k;
                int anchor = (int)(flat / NC);
                int l = (int)flat - anchor * NC;
                const float* row = pred + ((size_t)img * NANCH + anchor) * NCH;
                float cx = row[0], cy = row[1], w = row[2], h = row[3];
                float hw = __fmul_rn(0.5f, w), hh = __fmul_rn(0.5f, h);
                float4 rb;
                rb.x = __fsub_rn(cx, hw); rb.y = __fsub_rn(cy, hh);
                rb.z = __fadd_rn(cx, hw); rb.w = __fadd_rn(cy, hh);
                float off = __fmul_rn((float)l, 4.0f);
                float4 ob;
                ob.x = __fadd_rn(rb.x, off); ob.y = __fadd_rn(rb.y, off);
                ob.z = __fadd_rn(rb.z, off); ob.w = __fadd_rn(rb.w, off);
                rawb[r] = rb; offb[r] = ob;
                lab[r] = (unsigned char)l; keep[r] = 1;
                atomicAdd(&cnt[l], 1);
            } else { lab[r] = 255; keep[r] = 0; }
        }
        __syncthreads();
        if (tid == 0) { int run = 0; for (int l = 0; l < NC; l++) { start[l] = run; run += cnt[l]; } }
        __syncthreads();
        for (int r = tid; r < nvalid; r += 1024) {
            int l = lab[r];
            int p = start[l] + atomicAdd(&cnt2[l], 1);
            clist[p] = (unsigned short)r;
        }
        __syncthreads();

        const int warp = tid >> 5, lane = tid & 31;
        for (int l = warp; l < NC; l += 32) {
            const int b0 = start[l], kk = cnt[l];
            while (true) {
                unsigned long long bkey = 0ULL; int bidx = -1;
                for (int b = lane; b < kk; b += 32) {
                    int r = clist[b0 + b];
                    if (keep[r] == 1) {
                        unsigned long long kc = keys[r];
                        if (kc > bkey) { bkey = kc; bidx = b; }
                    }
                }
                #pragma unroll
                for (int o = 16; o > 0; o >>= 1) {
                    unsigned long long ok = __shfl_xor_sync(FULLM, bkey, o);
                    int ob = __shfl_xor_sync(FULLM, bidx, o);
                    if (ok > bkey) { bkey = ok; bidx = ob; }
                }
                if (bkey == 0ULL) break;
                int ra = clist[b0 + bidx];
                if (lane == 0) keep[ra] = 2;
                __syncwarp();
                float4 A = offb[ra];
                float areaA = __fmul_rn(__fsub_rn(A.z, A.x), __fsub_rn(A.w, A.y));
                for (int b = lane; b < kk; b += 32) {
                    int r = clist[b0 + b];
                    if (keep[r] == 1 && iou_gt(A, areaA, offb[r])) keep[r] = 0;
                }
                __syncwarp();
            }
        }
        __syncthreads();
        for (int i = tid; i < MAXC; i += 1024) keys[MAXC + i] = 0ULL;
        __syncthreads();
        for (int r = tid; r < nvalid; r += 1024) {
            if (keep[r] == 2) {
                unsigned long long k = keys[r];
                unsigned flat = 0xFFFFFFFFu - (unsigned)k;
                unsigned lo = ((0x1FFFFFu - flat) << 11) | (unsigned)r;
                int p = atomicAdd(&misc[0], 1);
                if (p < MAXC)
                    keys[MAXC + p] = (k & 0xFFFFFFFF00000000ULL) | (unsigned long long)lo;
            }
        }
        __syncthreads();
        int kept_n = min(misc[0], MAXC);
        int m = 1; while (m < kept_n) m <<= 1;
        bitonic_desc(keys + MAXC, m, tid, 1024);
        for (int d = tid; d < DET; d += 1024) {
            float o0=0.f,o1=0.f,o2=0.f,o3=0.f,o4=0.f,o5=0.f;
            unsigned long long k = (d < m) ? keys[MAXC + d] : 0ULL;
            if (k != 0ULL) {
                int r = (int)((unsigned)k & 0x7FFu);
                float4 rb = rawb[r];
                o0 = rb.x; o1 = rb.y; o2 = rb.z; o3 = rb.w;
                o4 = __uint_as_float((unsigned)(k >> 32));
                o5 = (float)lab[r];
            }
            float* o = out + ((size_t)img * DET + d) * 6;
            o[0]=o0; o[1]=o1; o[2]=o2; o[3]=o3; o[4]=o4; o[5]=o5;
        }
    }

    // reset all per-image counters for the next launch / graph replay
    __syncthreads();
    if (tid == 0) { g_count[img] = 0; g_kcnt[img] = 0; g_slow[img] = 0; }
    if (tid < NC) g_bcnt[img * NC + tid] = 0;
}

// ---------------- launch ----------------
extern "C" void kernel_launch(void* const* d_in, const int* in_sizes, int n_in,
                              void* d_out, int out_size) {
    const float* pred = (const float*)d_in[0];
    float* out = (float*)d_out;

    cudaFuncSetAttribute(k_final, cudaFuncAttributeMaxDynamicSharedMemorySize, SMEM_TOTAL);

    dim3 g1((NANCH + 255) / 256, NIMG);   // 99 x 8 = 792 blocks (proven best)
    k_extract<<<g1, 256>>>(pred);
    k_cls<<<(NIMG * NC + 3) / 4, 128>>>(pred);
    k_final<<<FINAL_GRID, 1024, SMEM_TOTAL>>>(pred, out);
    (void)in_sizes; (void)n_in; (void)out_size;
}